// round 7
// baseline (speedup 1.0000x reference)
#include <cuda_runtime.h>
#include <cuda_bf16.h>

// FinDiffNonUniform: yd[i,b] = sum_s w[i,s] * y[i + off[i,s], b]
// N=8192, B=4096, S=7, fp32.
//
// R7: ring-accumulator formulation. Each y row is read ONCE per thread
// (amp (TR+6)/TR = 1.19 @ TR=32) and scattered into 7 rotating register
// accumulators; loads stay FRONT-BATCHED in chunks of 8 (the issue
// structure that won in R1/R3/R6). All ring/window indices compile-time.

#define S_W 7
#define TR 32
#define TPB 256
#define VEC 2
#define NROWS (TR + 6)          // 38 y-rows per tile
#define CHUNK 8
#define NCHUNKS ((NROWS + CHUNK - 1) / CHUNK)   // 5
#define COLS_PER_BLOCK (TPB * VEC)

__global__ __launch_bounds__(TPB, 5)
void findiff_r7_kernel(const float* __restrict__ y,
                       const float* __restrict__ coef,
                       const int* __restrict__ offs,
                       float* __restrict__ out,
                       int N, int B)
{
    __shared__ float s_w[TR * S_W];
    __shared__ int   s_o[TR * S_W];
    __shared__ int   s_centered;

    const int t  = threadIdx.x;
    const int i0 = blockIdx.y * TR;

    if (t == 0) s_centered = 1;
    __syncthreads();

    for (int k = t; k < TR * S_W; k += TPB) {
        int gidx = i0 * S_W + k;
        if (gidx < N * S_W) {
            s_w[k] = coef[gidx];
            int o  = offs[gidx];
            s_o[k] = o;
            if (o != (k % S_W) - 3) s_centered = 0;
        } else {
            s_w[k] = 0.0f;
            s_o[k] = 0;
        }
    }
    __syncthreads();

    const int col = blockIdx.x * COLS_PER_BLOCK + t * VEC;
    if (col >= B) return;

    const bool interior = (i0 >= 3) && (i0 + TR + 2 <= N - 1) && s_centered;

    if (interior) {
        // ---- fast path: ring accumulators, offsets = s-3 ----
        const float* base  = y   + (size_t)(i0 - 3) * (size_t)B + col; // j_rel = 0
        float*       obase = out + (size_t)i0       * (size_t)B + col;

        float2 acc[7];
        float2 buf[CHUNK];

        #pragma unroll
        for (int c = 0; c < NCHUNKS; ++c) {
            const int j0 = c * CHUNK;

            // front-batched loads for this chunk
            #pragma unroll
            for (int k = 0; k < CHUNK; ++k) {
                if (j0 + k < NROWS)
                    buf[k] = *reinterpret_cast<const float2*>(
                                 base + (size_t)(j0 + k) * (size_t)B);
            }

            // accumulate + store completed rows
            #pragma unroll
            for (int k = 0; k < CHUNK; ++k) {
                const int j = j0 + k;             // 0..NROWS-1 (compile-time)
                if (j >= NROWS) break;
                const float2 v = buf[k];

                #pragma unroll
                for (int s = 0; s < S_W; ++s) {
                    const int i_rel = j - s;      // output row touched
                    if (i_rel >= 0 && i_rel < TR) {
                        const float w = s_w[i_rel * S_W + s];
                        float2& a = acc[i_rel % 7];
                        if (s == 0) {             // first contribution
                            a.x = w * v.x;
                            a.y = w * v.y;
                        } else {
                            a.x = fmaf(w, v.x, a.x);
                            a.y = fmaf(w, v.y, a.y);
                        }
                    }
                }

                const int done = j - 6;           // row completed this step
                if (done >= 0 && done < TR)
                    *reinterpret_cast<float2*>(
                        obase + (size_t)done * (size_t)B) = acc[done % 7];
            }
        }
    } else {
        // ---- generic path: per-row gather (boundary tiles only) ----
        for (int r = 0; r < TR; ++r) {
            const int i = i0 + r;
            if (i >= N) break;
            float2 acc = make_float2(0.f, 0.f);
            #pragma unroll
            for (int s = 0; s < S_W; ++s) {
                const float w = s_w[r * S_W + s];
                const int   j = i + s_o[r * S_W + s];
                const float2 v = *reinterpret_cast<const float2*>(
                    y + (size_t)j * (size_t)B + col);
                acc.x = fmaf(w, v.x, acc.x);
                acc.y = fmaf(w, v.y, acc.y);
            }
            *reinterpret_cast<float2*>(out + (size_t)i * (size_t)B + col) = acc;
        }
    }
}

// Fully generic scalar fallback (any N, B).
__global__ void findiff_scalar_kernel(const float* __restrict__ y,
                                      const float* __restrict__ coef,
                                      const int* __restrict__ offs,
                                      float* __restrict__ out,
                                      int N, int B)
{
    const long long total = (long long)N * B;
    for (long long idx = (long long)blockIdx.x * blockDim.x + threadIdx.x;
         idx < total;
         idx += (long long)gridDim.x * blockDim.x) {
        const int i = (int)(idx / B);
        const int b = (int)(idx % B);
        float acc = 0.f;
        #pragma unroll
        for (int s = 0; s < S_W; ++s) {
            const float w = coef[i * S_W + s];
            const int   j = i + offs[i * S_W + s];
            acc = fmaf(w, y[(size_t)j * (size_t)B + b], acc);
        }
        out[idx] = acc;
    }
}

extern "C" void kernel_launch(void* const* d_in, const int* in_sizes, int n_in,
                              void* d_out, int out_size)
{
    const float* y    = (const float*)d_in[0];
    const float* coef = (const float*)d_in[1];
    const int*   offs = (const int*)d_in[2];
    float* out = (float*)d_out;

    const int N = in_sizes[1] / S_W;       // all_coefficients is [N, 7]
    const int B = in_sizes[0] / N;         // y is [N, B]

    if ((B % COLS_PER_BLOCK) == 0 && (N % TR) == 0) {
        dim3 grid(B / COLS_PER_BLOCK, N / TR);
        findiff_r7_kernel<<<grid, TPB>>>(y, coef, offs, out, N, B);
    } else {
        const long long total = (long long)N * B;
        int blocks = (int)((total + 255) / 256);
        if (blocks > 65535 * 32) blocks = 65535 * 32;
        findiff_scalar_kernel<<<blocks, 256>>>(y, coef, offs, out, N, B);
    }
}

// round 8
// speedup vs baseline: 1.0930x; 1.0930x over previous
#include <cuda_runtime.h>
#include <cuda_bf16.h>

// FinDiffNonUniform: yd[i,b] = sum_s w[i,s] * y[i + off[i,s], b]
// N=8192, B=4096, S=7, fp32.
//
// R8: concurrency is the only lever that has moved DRAM% (TR=8/grid-8192
// variants beat all traffic-optimized ones). Raise occupancy to ~7 CTAs/SM:
//  - scalar lanes (VEC=1): window = TR+6 single floats (half the regs),
//    warp still moves one full 128B line per row (coalescing unchanged)
//  - compile-time stride (B templated): window loads become LDG [base+imm],
//    removing ~22 IMAD address computations and their registers
// TR=16 -> amp 1.375, grid (16, 512) = 8192 CTAs.

#define S_W 7
#define TR 16
#define TPB 256
#define WIN (TR + 6)               // 22-row window
#define COLS_PER_BLOCK TPB

template <int BS>                   // compile-time row stride (elements)
__global__ __launch_bounds__(TPB, 7)
void findiff_r8_kernel(const float* __restrict__ y,
                       const float* __restrict__ coef,
                       const int* __restrict__ offs,
                       float* __restrict__ out,
                       int N)
{
    __shared__ float s_w[TR * S_W];
    __shared__ int   s_o[TR * S_W];
    __shared__ int   s_centered;

    const int t  = threadIdx.x;
    const int i0 = blockIdx.y * TR;

    if (t == 0) s_centered = 1;
    __syncthreads();

    if (t < TR * S_W) {
        const int gidx = i0 * S_W + t;
        s_w[t] = coef[gidx];
        const int o = offs[gidx];
        s_o[t] = o;
        if (o != (t % S_W) - 3) s_centered = 0;
    }
    __syncthreads();

    const int col = blockIdx.x * COLS_PER_BLOCK + t;

    const bool interior = (i0 >= 3) && (i0 + TR + 2 <= N - 1) && s_centered;

    if (interior) {
        // ---- fast path: front-batched scalar window, offsets = s-3 ----
        const float* base  = y   + (size_t)(i0 - 3) * (size_t)BS + col;
        float*       obase = out + (size_t)i0       * (size_t)BS + col;

        float win[WIN];
        #pragma unroll
        for (int k = 0; k < WIN; ++k)
            win[k] = base[(size_t)k * BS];       // LDG [base + imm]

        #pragma unroll
        for (int r = 0; r < TR; ++r) {
            float acc = 0.f;
            #pragma unroll
            for (int s = 0; s < S_W; ++s)
                acc = fmaf(s_w[r * S_W + s], win[r + s], acc);
            obase[(size_t)r * BS] = acc;         // STG [obase + imm]
        }
    } else {
        // ---- generic path: per-row gather (boundary tiles only) ----
        #pragma unroll
        for (int r = 0; r < TR; ++r) {
            const int i = i0 + r;
            if (i >= N) break;
            float acc = 0.f;
            #pragma unroll
            for (int s = 0; s < S_W; ++s) {
                const float w = s_w[r * S_W + s];
                const int   j = i + s_o[r * S_W + s];
                acc = fmaf(w, y[(size_t)j * (size_t)BS + col], acc);
            }
            out[(size_t)i * (size_t)BS + col] = acc;
        }
    }
}

// Fully generic scalar fallback (any N, B).
__global__ void findiff_scalar_kernel(const float* __restrict__ y,
                                      const float* __restrict__ coef,
                                      const int* __restrict__ offs,
                                      float* __restrict__ out,
                                      int N, int B)
{
    const long long total = (long long)N * B;
    for (long long idx = (long long)blockIdx.x * blockDim.x + threadIdx.x;
         idx < total;
         idx += (long long)gridDim.x * blockDim.x) {
        const int i = (int)(idx / B);
        const int b = (int)(idx % B);
        float acc = 0.f;
        #pragma unroll
        for (int s = 0; s < S_W; ++s) {
            const float w = coef[i * S_W + s];
            const int   j = i + offs[i * S_W + s];
            acc = fmaf(w, y[(size_t)j * (size_t)B + b], acc);
        }
        out[idx] = acc;
    }
}

extern "C" void kernel_launch(void* const* d_in, const int* in_sizes, int n_in,
                              void* d_out, int out_size)
{
    const float* y    = (const float*)d_in[0];
    const float* coef = (const float*)d_in[1];
    const int*   offs = (const int*)d_in[2];
    float* out = (float*)d_out;

    const int N = in_sizes[1] / S_W;       // all_coefficients is [N, 7]
    const int B = in_sizes[0] / N;         // y is [N, B]

    if (B == 4096 && (N % TR) == 0 && N >= 3 * TR) {
        dim3 grid(4096 / COLS_PER_BLOCK, N / TR);
        findiff_r8_kernel<4096><<<grid, TPB>>>(y, coef, offs, out, N);
    } else if (B == 2048 && (N % TR) == 0 && N >= 3 * TR) {
        dim3 grid(2048 / COLS_PER_BLOCK, N / TR);
        findiff_r8_kernel<2048><<<grid, TPB>>>(y, coef, offs, out, N);
    } else {
        const long long total = (long long)N * B;
        int blocks = (int)((total + 255) / 256);
        if (blocks > 65535 * 32) blocks = 65535 * 32;
        findiff_scalar_kernel<<<blocks, 256>>>(y, coef, offs, out, N, B);
    }
}

// round 9
// speedup vs baseline: 1.2789x; 1.1701x over previous
#include <cuda_runtime.h>
#include <cuda_bf16.h>

// FinDiffNonUniform: yd[i,b] = sum_s w[i,s] * y[i + off[i,s], b]
// N=8192, B=4096, S=7, fp32.
//
// R9: R1/R3/R6 sit on the full-chip LTS cap (~6300 B/cyc: amp-reads +
// stores + fill + writeback ~= 600MB / 45us ~= 13 TB/s). Keep the winning
// R3 structure (TR=8, float2 lanes, front-batched 14-row window, ~70% occ)
// and improve L2 behavior of the halo (amplification) stream: row-tiles on
// blockIdx.x so consecutively-scheduled CTAs are row-neighbors within the
// same column stripe -> halo lines re-read while still L2-hot.

#define S_W 7
#define TR 8
#define TPB 256
#define VEC 2
#define WIN (TR + 6)               // 14-row window
#define COLS_PER_BLOCK (TPB * VEC)

__global__ __launch_bounds__(TPB, 6)
void findiff_r9_kernel(const float* __restrict__ y,
                       const float* __restrict__ coef,
                       const int* __restrict__ offs,
                       float* __restrict__ out,
                       int N, int B)
{
    __shared__ float s_w[TR * S_W];
    __shared__ int   s_o[TR * S_W];
    __shared__ int   s_centered;

    const int t  = threadIdx.x;
    const int i0 = blockIdx.x * TR;            // row tile on FAST axis

    if (t == 0) s_centered = 1;
    __syncthreads();

    if (t < TR * S_W) {
        const int gidx = i0 * S_W + t;
        if (gidx < N * S_W) {
            s_w[t] = __ldg(&coef[gidx]);
            const int o = __ldg(&offs[gidx]);
            s_o[t] = o;
            if (o != (t % S_W) - 3) s_centered = 0;
        } else {
            s_w[t] = 0.0f;
            s_o[t] = 0;
        }
    }
    __syncthreads();

    const int col = blockIdx.y * COLS_PER_BLOCK + t * VEC;
    if (col >= B) return;

    const bool interior = (i0 >= 3) && (i0 + TR + 2 <= N - 1) && s_centered;

    if (interior) {
        // ---- fast path: front-batched register window, offsets = s-3 ----
        float2 win[WIN];
        const float* base = y + (size_t)(i0 - 3) * (size_t)B + col;
        #pragma unroll
        for (int k = 0; k < WIN; ++k)
            win[k] = *reinterpret_cast<const float2*>(base + (size_t)k * (size_t)B);

        float* obase = out + (size_t)i0 * (size_t)B + col;
        #pragma unroll
        for (int r = 0; r < TR; ++r) {
            float2 acc = make_float2(0.f, 0.f);
            #pragma unroll
            for (int s = 0; s < S_W; ++s) {
                const float  w = s_w[r * S_W + s];
                const float2 v = win[r + s];
                acc.x = fmaf(w, v.x, acc.x);
                acc.y = fmaf(w, v.y, acc.y);
            }
            *reinterpret_cast<float2*>(obase + (size_t)r * (size_t)B) = acc;
        }
    } else {
        // ---- generic path: per-row gather (boundary tiles only) ----
        #pragma unroll
        for (int r = 0; r < TR; ++r) {
            const int i = i0 + r;
            if (i >= N) break;
            float2 acc = make_float2(0.f, 0.f);
            #pragma unroll
            for (int s = 0; s < S_W; ++s) {
                const float w = s_w[r * S_W + s];
                const int   j = i + s_o[r * S_W + s];
                const float2 v = *reinterpret_cast<const float2*>(
                    y + (size_t)j * (size_t)B + col);
                acc.x = fmaf(w, v.x, acc.x);
                acc.y = fmaf(w, v.y, acc.y);
            }
            *reinterpret_cast<float2*>(out + (size_t)i * (size_t)B + col) = acc;
        }
    }
}

// Fully generic scalar fallback (any N, B).
__global__ void findiff_scalar_kernel(const float* __restrict__ y,
                                      const float* __restrict__ coef,
                                      const int* __restrict__ offs,
                                      float* __restrict__ out,
                                      int N, int B)
{
    const long long total = (long long)N * B;
    for (long long idx = (long long)blockIdx.x * blockDim.x + threadIdx.x;
         idx < total;
         idx += (long long)gridDim.x * blockDim.x) {
        const int i = (int)(idx / B);
        const int b = (int)(idx % B);
        float acc = 0.f;
        #pragma unroll
        for (int s = 0; s < S_W; ++s) {
            const float w = coef[i * S_W + s];
            const int   j = i + offs[i * S_W + s];
            acc = fmaf(w, y[(size_t)j * (size_t)B + b], acc);
        }
        out[idx] = acc;
    }
}

extern "C" void kernel_launch(void* const* d_in, const int* in_sizes, int n_in,
                              void* d_out, int out_size)
{
    const float* y    = (const float*)d_in[0];
    const float* coef = (const float*)d_in[1];
    const int*   offs = (const int*)d_in[2];
    float* out = (float*)d_out;

    const int N = in_sizes[1] / S_W;       // all_coefficients is [N, 7]
    const int B = in_sizes[0] / N;         // y is [N, B]

    if ((B % COLS_PER_BLOCK) == 0) {
        dim3 grid((N + TR - 1) / TR, B / COLS_PER_BLOCK);
        findiff_r9_kernel<<<grid, TPB>>>(y, coef, offs, out, N, B);
    } else {
        const long long total = (long long)N * B;
        int blocks = (int)((total + 255) / 256);
        if (blocks > 65535 * 32) blocks = 65535 * 32;
        findiff_scalar_kernel<<<blocks, 256>>>(y, coef, offs, out, N, B);
    }
}